// round 14
// baseline (speedup 1.0000x reference)
#include <cuda_runtime.h>
#include <cuda_fp16.h>
#include <cstdint>
#include <math.h>

#define BB 32
#define NN 12
#define SS 512
#define DD 256
#define AA 96

// ---------------- scratch (device globals, fp16 hi planes) -------------------
static __device__ __align__(16) __half g_qh[NN * SS * DD];
static __device__ __align__(16) __half g_ETh[NN * DD * SS];
static __device__ float g_cs[NN * DD];
static __device__ __align__(16) __half g_kvh[(size_t)BB * NN * DD * DD];
static __device__ __align__(16) __half g_Ph[(size_t)BB * NN * DD * DD];

// ---------------- helpers ----------------------------------------------------
__device__ __forceinline__ uint32_t smem_u32(const void* p) {
    uint32_t a;
    asm("{ .reg .u64 t; cvta.to.shared.u64 t, %1; cvt.u32.u64 %0, t; }" : "=r"(a) : "l"(p));
    return a;
}
__device__ __forceinline__ void ldsm4(uint32_t* r, uint32_t a) {
    asm volatile("ldmatrix.sync.aligned.m8n8.x4.shared.b16 {%0,%1,%2,%3}, [%4];"
                 : "=r"(r[0]), "=r"(r[1]), "=r"(r[2]), "=r"(r[3]) : "r"(a));
}
__device__ __forceinline__ void ldsm4t(uint32_t* r, uint32_t a) {
    asm volatile("ldmatrix.sync.aligned.m8n8.x4.trans.shared.b16 {%0,%1,%2,%3}, [%4];"
                 : "=r"(r[0]), "=r"(r[1]), "=r"(r[2]), "=r"(r[3]) : "r"(a));
}
__device__ __forceinline__ void mma16816(float* c, const uint32_t* a, const uint32_t* b) {
    asm volatile("mma.sync.aligned.m16n8k16.row.col.f32.f16.f16.f32 "
                 "{%0,%1,%2,%3}, {%4,%5,%6,%7}, {%8,%9}, {%0,%1,%2,%3};"
                 : "+f"(c[0]), "+f"(c[1]), "+f"(c[2]), "+f"(c[3])
                 : "r"(a[0]), "r"(a[1]), "r"(a[2]), "r"(a[3]), "r"(b[0]), "r"(b[1]));
}
__device__ __forceinline__ uint32_t pack2h(float x, float y) {
    __half2 hv; hv.x = __float2half_rn(x); hv.y = __float2half_rn(y);
    return *(uint32_t*)&hv;
}
#define CP16(dst, src) \
    asm volatile("cp.async.cg.shared.global [%0], [%1], 16;" :: "r"(dst), "l"(src))
#define CP_COMMIT() asm volatile("cp.async.commit_group;" ::: "memory")
#define CP_WAIT1()  asm volatile("cp.async.wait_group 1;" ::: "memory")

// ---------------- qk kernel: q hi plane + ET hi plane -------------------------
#define QROWS 32
__global__ __launch_bounds__(256)
void qk_kernel(const float* __restrict__ emb,
               const float* __restrict__ Wqk,
               const float* __restrict__ bqk)
{
    int n = blockIdx.x / (SS / QROWS);
    int s0 = (blockIdx.x % (SS / QROWS)) * QROWS;

    __shared__ float se[QROWS][AA];
    __shared__ float es[QROWS][257];

    int tid = threadIdx.x;
    for (int i = tid; i < QROWS * AA; i += 256)
        se[i / AA][i % AA] = emb[((size_t)(n * SS + s0)) * AA + i];
    __syncthreads();

    int sy = tid >> 5;
    int dx = tid & 31;

    float acc[4][8];
#pragma unroll
    for (int j = 0; j < 8; ++j) {
        float b = bqk[j * 32 + dx];
#pragma unroll
        for (int i = 0; i < 4; ++i) acc[i][j] = b;
    }
#pragma unroll 2
    for (int a = 0; a < AA; ++a) {
        float w[8];
#pragma unroll
        for (int j = 0; j < 8; ++j) w[j] = Wqk[a * DD + j * 32 + dx];
        float sv0 = se[sy * 4 + 0][a], sv1 = se[sy * 4 + 1][a];
        float sv2 = se[sy * 4 + 2][a], sv3 = se[sy * 4 + 3][a];
#pragma unroll
        for (int j = 0; j < 8; ++j) {
            acc[0][j] = fmaf(sv0, w[j], acc[0][j]);
            acc[1][j] = fmaf(sv1, w[j], acc[1][j]);
            acc[2][j] = fmaf(sv2, w[j], acc[2][j]);
            acc[3][j] = fmaf(sv3, w[j], acc[3][j]);
        }
    }

#pragma unroll
    for (int i = 0; i < 4; ++i) {
        float loc = 0.0f;
#pragma unroll
        for (int j = 0; j < 8; ++j) { acc[i][j] = expf(acc[i][j]); loc += acc[i][j]; }
#pragma unroll
        for (int off = 16; off > 0; off >>= 1) loc += __shfl_xor_sync(0xffffffff, loc, off);
        float inv = 1.0f / loc;
        int s = s0 + sy * 4 + i;
#pragma unroll
        for (int j = 0; j < 8; ++j) {
            size_t idx = ((size_t)(n * SS + s)) * DD + j * 32 + dx;
            g_qh[idx] = __float2half_rn(acc[i][j] * inv);
            es[sy * 4 + i][j * 32 + dx] = acc[i][j];
        }
    }
    __syncthreads();

    int dq = tid >> 3;
    int sq = (tid & 7) * 4;
#pragma unroll
    for (int pass = 0; pass < 8; ++pass) {
        int d = pass * 32 + dq;
        __half2 a = __halves2half2(__float2half_rn(es[sq + 0][d]), __float2half_rn(es[sq + 1][d]));
        __half2 b = __halves2half2(__float2half_rn(es[sq + 2][d]), __float2half_rn(es[sq + 3][d]));
        uint2 uh; uh.x = *(uint32_t*)&a; uh.y = *(uint32_t*)&b;
        *(uint2*)&g_ETh[((size_t)n * DD + d) * SS + s0 + sq] = uh;
    }
}

// colsum over hi plane (matches GEMM1's operand exactly)
__global__ void colsum_kernel()
{
    int r = blockIdx.x * 8 + (threadIdx.x >> 5);
    int l = threadIdx.x & 31;
    const uint4* ph = (const uint4*)(g_ETh + (size_t)r * SS);
    float s = 0.0f;
#pragma unroll
    for (int c = 0; c < 2; ++c) {
        uint4 a = ph[l + c * 32];
        const __half2* pa = (const __half2*)&a;
#pragma unroll
        for (int j = 0; j < 4; ++j) {
            float2 fa = __half22float2(pa[j]);
            s += fa.x + fa.y;
        }
    }
#pragma unroll
    for (int off = 16; off > 0; off >>= 1) s += __shfl_xor_sync(0xffffffff, s, off);
    if (l == 0) g_cs[r] = s;
}

// ---------------- warp-MMA fp16 batched GEMM (single-pass, K=64 chunks) ------
// 3-stage cp.async ring, wait_group 1, one barrier per 64-K chunk.
// BF32: B fp32 (in-kernel convert to hi) else fp16 hi plane via cp.async.
// OMODE: 0 = fp32 out + bias; 1 = half hi + row scale; 2 = half hi.
#define KC 64
#define A_STR 144     // 64 halfs (128B) + 16B pad; conflict-free ldsm
#define B_STR 272     // 128 halfs (256B) + 16B pad
#define SM_AH 0
#define SM_BH (128 * A_STR)                 // 18432
#define SM_STAGE (SM_BH + 64 * B_STR)       // 35840
#define SM_PIPE (3 * SM_STAGE)              // 107520

template<bool BF32, int OMODE>
__global__ __launch_bounds__(256, 2)
void gemm_mma(const __half* __restrict__ Ahg,
              const void* __restrict__ Bg,
              void* __restrict__ Cg,
              int K, int ldb, int ldc,
              long aStride, int aMod, long bStride, int bMod, long cStride,
              const float* __restrict__ scaleBase, int scaleMod,
              const float* __restrict__ bias)
{
    extern __shared__ __align__(16) char smem[];

    int z = blockIdx.z;
    const __half* Ah = Ahg + (long)(aMod ? (z % aMod) : z) * aStride;
    int m0 = blockIdx.y * 128, n0 = blockIdx.x * 128;

    int tid = threadIdx.x, lane = tid & 31, wid = tid >> 5;
    int wm = wid >> 1, wn = wid & 1;       // warp tile 32(M) x 64(N)

    uint32_t sb = smem_u32(smem);

    // A cp.async map: 2 threads/row, 64B each (4x CP16)
    int arow = tid >> 1;
    int ah4 = (tid & 1);                    // half of the 128B row
    const __half* aSrcH = Ah + (size_t)(m0 + arow) * K + ah4 * 32;
    uint32_t aDstH = sb + SM_AH + arow * A_STR + ah4 * 64;

    // B maps: 4 threads/row
    int brow = tid >> 2;
    int b4 = tid & 3;
    const __half* bSrcH = nullptr;
    const float* bPtr = nullptr;
    uint32_t bDst = 0, bOffH = 0;
    if (BF32) {
        bPtr = (const float*)Bg + (long)(bMod ? (z % bMod) : z) * bStride
             + (long)brow * ldb + n0 + b4 * 32;
        bOffH = SM_BH + brow * B_STR + b4 * 64;
    } else {
        bSrcH = (const __half*)Bg + (long)(bMod ? (z % bMod) : z) * bStride
              + (size_t)brow * ldb + n0 + b4 * 32;
        bDst = sb + SM_BH + brow * B_STR + b4 * 64;
    }

    uint32_t aFH[2], bFH[4];
#pragma unroll
    for (int t = 0; t < 2; ++t)
        aFH[t] = SM_AH + (uint32_t)((wm * 32 + t * 16 + (lane & 15)) * A_STR + (lane >> 4) * 16);
#pragma unroll
    for (int p = 0; p < 4; ++p)
        bFH[p] = SM_BH + (uint32_t)((lane & 15) * B_STR + (wn * 64 + p * 16 + (lane >> 4) * 8) * 2);

    float acc[2][8][4];
#pragma unroll
    for (int t = 0; t < 2; ++t)
#pragma unroll
        for (int nt = 0; nt < 8; ++nt)
#pragma unroll
            for (int j = 0; j < 4; ++j) acc[t][nt][j] = 0.0f;

    auto cpAsyncLoad = [&](int kc, uint32_t bufOff) {
        const __half* sh = aSrcH + kc * KC;
#pragma unroll
        for (int u = 0; u < 4; ++u)
            CP16(aDstH + bufOff + u * 16, sh + u * 8);
        if (!BF32) {
            const __half* sbp = bSrcH + (size_t)kc * KC * ldb;
#pragma unroll
            for (int u = 0; u < 4; ++u)
                CP16(bDst + bufOff + u * 16, sbp + u * 8);
        }
    };
    auto bConvStore = [&](int kc, uint32_t bufOff) {
        const float* bp = bPtr + (size_t)kc * KC * ldb;
#pragma unroll
        for (int u = 0; u < 4; ++u) {
            float4 v0 = *(const float4*)(bp + u * 8);
            float4 v1 = *(const float4*)(bp + u * 8 + 4);
            *(uint4*)(smem + bufOff + bOffH + u * 16) = make_uint4(
                pack2h(v0.x, v0.y), pack2h(v0.z, v0.w),
                pack2h(v1.x, v1.y), pack2h(v1.z, v1.w));
        }
    };
    auto mmaStep = [&](int kk, uint32_t bufOff) {
        uint32_t ah[2][4], bf[4][4];
#pragma unroll
        for (int t = 0; t < 2; ++t)
            ldsm4(ah[t], sb + bufOff + aFH[t] + kk * 32);
#pragma unroll
        for (int p = 0; p < 4; ++p)
            ldsm4t(bf[p], sb + bufOff + bFH[p] + kk * 16 * B_STR);
#pragma unroll
        for (int t = 0; t < 2; ++t)
#pragma unroll
            for (int nt = 0; nt < 8; ++nt)
                mma16816(acc[t][nt], ah[t], &bf[nt >> 1][(nt & 1) * 2]);
    };

    int KT = K / KC;

    cpAsyncLoad(0, 0);
    CP_COMMIT();
    cpAsyncLoad(1, SM_STAGE);
    CP_COMMIT();
    if (BF32) bConvStore(0, 0);

    int cur = 0;
    for (int kc = 0; kc < KT; ++kc) {
        uint32_t curOff = (uint32_t)cur * SM_STAGE;
        CP_WAIT1();
        __syncthreads();
        int pf = kc + 2;
        if (pf < KT) {
            int pfs = pf - 3 * (pf / 3);
            cpAsyncLoad(pf, (uint32_t)pfs * SM_STAGE);
            CP_COMMIT();
        }
        mmaStep(0, curOff);
        mmaStep(1, curOff);
        if (BF32 && kc + 1 < KT) {
            int ns = (cur + 1 == 3) ? 0 : cur + 1;
            bConvStore(kc + 1, (uint32_t)ns * SM_STAGE);
        }
        mmaStep(2, curOff);
        mmaStep(3, curOff);
        cur = (cur + 1 == 3) ? 0 : cur + 1;
    }

    // ---- epilogue ----
    const float* sp = (OMODE == 1)
        ? scaleBase + (long)(scaleMod ? (z % scaleMod) : z) * DD : nullptr;
#pragma unroll
    for (int t = 0; t < 2; ++t) {
        int row = m0 + wm * 32 + t * 16 + (lane >> 2);
        float s0 = 1.0f, s1 = 1.0f;
        if (OMODE == 1) { s0 = 1.0f / sp[row]; s1 = 1.0f / sp[row + 8]; }
#pragma unroll
        for (int nt = 0; nt < 8; ++nt) {
            int col = n0 + wn * 64 + nt * 8 + (lane & 3) * 2;
            float v0 = acc[t][nt][0] * s0, v1 = acc[t][nt][1] * s0;
            float v2 = acc[t][nt][2] * s1, v3 = acc[t][nt][3] * s1;
            if (OMODE == 0) {
                float* C = (float*)Cg + (long)z * cStride;
                float2 bb = *(const float2*)(bias + col);
                *(float2*)&C[(long)row * ldc + col] = make_float2(v0 + bb.x, v1 + bb.y);
                *(float2*)&C[(long)(row + 8) * ldc + col] = make_float2(v2 + bb.x, v3 + bb.y);
            } else {
                __half* Ch = (__half*)Cg + (long)z * cStride;
                *(__half2*)&Ch[(long)row * ldc + col] =
                    __halves2half2(__float2half_rn(v0), __float2half_rn(v1));
                *(__half2*)&Ch[(long)(row + 8) * ldc + col] =
                    __halves2half2(__float2half_rn(v2), __float2half_rn(v3));
            }
        }
    }
}

// ---------------- launch -----------------------------------------------------
extern "C" void kernel_launch(void* const* d_in, const int* in_sizes, int n_in,
                              void* d_out, int out_size)
{
    const float* value = (const float*)d_in[0];
    const float* emb   = (const float*)d_in[1];
    const float* Wqk   = (const float*)d_in[2];
    const float* bqk   = (const float*)d_in[3];
    const float* Wv    = (const float*)d_in[4];
    const float* bv    = (const float*)d_in[5];
    float* out = (float*)d_out;

    void *pqh, *pETh, *pcs, *pkvh, *pPh;
    cudaGetSymbolAddress(&pqh, g_qh);
    cudaGetSymbolAddress(&pETh, g_ETh);
    cudaGetSymbolAddress(&pcs, g_cs);
    cudaGetSymbolAddress(&pkvh, g_kvh);
    cudaGetSymbolAddress(&pPh, g_Ph);

    static int smemSet = 0;
    if (!smemSet) {
        cudaFuncSetAttribute(gemm_mma<true, 1>,  cudaFuncAttributeMaxDynamicSharedMemorySize, SM_PIPE);
        cudaFuncSetAttribute(gemm_mma<true, 2>,  cudaFuncAttributeMaxDynamicSharedMemorySize, SM_PIPE);
        cudaFuncSetAttribute(gemm_mma<false, 0>, cudaFuncAttributeMaxDynamicSharedMemorySize, SM_PIPE);
        smemSet = 1;
    }

    qk_kernel<<<NN * (SS / QROWS), 256>>>(emb, Wqk, bqk);
    colsum_kernel<<<NN * DD / 8, 256>>>();

    // GEMM1: kv = (ETh @ value_hi) / colsum  -> kv hi plane
    gemm_mma<true, 1><<<dim3(2, 2, BB * NN), 256, SM_PIPE>>>(
        (const __half*)pETh, value,
        pkvh,
        SS, DD, DD,
        (long)DD * SS, NN,
        (long)SS * DD, 0,
        (long)DD * DD,
        (const float*)pcs, NN, nullptr);

    // GEMM2: P = kv @ Wv_hi  -> P hi plane
    gemm_mma<true, 2><<<dim3(2, 2, BB * NN), 256, SM_PIPE>>>(
        (const __half*)pkvh, Wv,
        pPh,
        DD, DD, DD,
        (long)DD * DD, 0,
        0L, 0,
        (long)DD * DD,
        nullptr, 0, nullptr);

    // GEMM3: out = q @ P + bv  (fp32 out)
    gemm_mma<false, 0><<<dim3(2, 4, BB * NN), 256, SM_PIPE>>>(
        (const __half*)pqh, pPh,
        out,
        DD, DD, DD,
        (long)SS * DD, NN,
        (long)DD * DD, 0,
        (long)SS * DD,
        nullptr, 0, bv);
}

// round 15
// speedup vs baseline: 1.2069x; 1.2069x over previous
#include <cuda_runtime.h>
#include <cuda_fp16.h>
#include <cstdint>
#include <math.h>

#define BB 32
#define NN 12
#define SS 512
#define DD 256
#define AA 96

// ---------------- scratch (device globals, fp16 hi planes) -------------------
static __device__ __align__(16) __half g_qh[NN * SS * DD];
static __device__ __align__(16) __half g_ETh[NN * DD * SS];
static __device__ float g_cs[NN * DD];
static __device__ __align__(16) __half g_kvh[(size_t)BB * NN * DD * DD];
static __device__ __align__(16) __half g_Ph[(size_t)BB * NN * DD * DD];

// ---------------- helpers ----------------------------------------------------
__device__ __forceinline__ uint32_t smem_u32(const void* p) {
    uint32_t a;
    asm("{ .reg .u64 t; cvta.to.shared.u64 t, %1; cvt.u32.u64 %0, t; }" : "=r"(a) : "l"(p));
    return a;
}
__device__ __forceinline__ void ldsm4(uint32_t* r, uint32_t a) {
    asm volatile("ldmatrix.sync.aligned.m8n8.x4.shared.b16 {%0,%1,%2,%3}, [%4];"
                 : "=r"(r[0]), "=r"(r[1]), "=r"(r[2]), "=r"(r[3]) : "r"(a));
}
__device__ __forceinline__ void ldsm4t(uint32_t* r, uint32_t a) {
    asm volatile("ldmatrix.sync.aligned.m8n8.x4.trans.shared.b16 {%0,%1,%2,%3}, [%4];"
                 : "=r"(r[0]), "=r"(r[1]), "=r"(r[2]), "=r"(r[3]) : "r"(a));
}
__device__ __forceinline__ void mma16816(float* c, const uint32_t* a, const uint32_t* b) {
    asm volatile("mma.sync.aligned.m16n8k16.row.col.f32.f16.f16.f32 "
                 "{%0,%1,%2,%3}, {%4,%5,%6,%7}, {%8,%9}, {%0,%1,%2,%3};"
                 : "+f"(c[0]), "+f"(c[1]), "+f"(c[2]), "+f"(c[3])
                 : "r"(a[0]), "r"(a[1]), "r"(a[2]), "r"(a[3]), "r"(b[0]), "r"(b[1]));
}
__device__ __forceinline__ uint32_t pack2h(float x, float y) {
    __half2 hv; hv.x = __float2half_rn(x); hv.y = __float2half_rn(y);
    return *(uint32_t*)&hv;
}
#define CP16(dst, src) \
    asm volatile("cp.async.cg.shared.global [%0], [%1], 16;" :: "r"(dst), "l"(src))
#define CP_COMMIT() asm volatile("cp.async.commit_group;" ::: "memory")
#define CP_WAIT1()  asm volatile("cp.async.wait_group 1;" ::: "memory")

// ---------------- qk kernel: q hi plane + ET hi plane -------------------------
#define QROWS 32
__global__ __launch_bounds__(256)
void qk_kernel(const float* __restrict__ emb,
               const float* __restrict__ Wqk,
               const float* __restrict__ bqk)
{
    int n = blockIdx.x / (SS / QROWS);
    int s0 = (blockIdx.x % (SS / QROWS)) * QROWS;

    __shared__ float se[QROWS][AA];
    __shared__ float es[QROWS][257];

    int tid = threadIdx.x;
    for (int i = tid; i < QROWS * AA; i += 256)
        se[i / AA][i % AA] = emb[((size_t)(n * SS + s0)) * AA + i];
    __syncthreads();

    int sy = tid >> 5;
    int dx = tid & 31;

    float acc[4][8];
#pragma unroll
    for (int j = 0; j < 8; ++j) {
        float b = bqk[j * 32 + dx];
#pragma unroll
        for (int i = 0; i < 4; ++i) acc[i][j] = b;
    }
#pragma unroll 2
    for (int a = 0; a < AA; ++a) {
        float w[8];
#pragma unroll
        for (int j = 0; j < 8; ++j) w[j] = Wqk[a * DD + j * 32 + dx];
        float sv0 = se[sy * 4 + 0][a], sv1 = se[sy * 4 + 1][a];
        float sv2 = se[sy * 4 + 2][a], sv3 = se[sy * 4 + 3][a];
#pragma unroll
        for (int j = 0; j < 8; ++j) {
            acc[0][j] = fmaf(sv0, w[j], acc[0][j]);
            acc[1][j] = fmaf(sv1, w[j], acc[1][j]);
            acc[2][j] = fmaf(sv2, w[j], acc[2][j]);
            acc[3][j] = fmaf(sv3, w[j], acc[3][j]);
        }
    }

#pragma unroll
    for (int i = 0; i < 4; ++i) {
        float loc = 0.0f;
#pragma unroll
        for (int j = 0; j < 8; ++j) { acc[i][j] = expf(acc[i][j]); loc += acc[i][j]; }
#pragma unroll
        for (int off = 16; off > 0; off >>= 1) loc += __shfl_xor_sync(0xffffffff, loc, off);
        float inv = 1.0f / loc;
        int s = s0 + sy * 4 + i;
#pragma unroll
        for (int j = 0; j < 8; ++j) {
            size_t idx = ((size_t)(n * SS + s)) * DD + j * 32 + dx;
            g_qh[idx] = __float2half_rn(acc[i][j] * inv);
            es[sy * 4 + i][j * 32 + dx] = acc[i][j];
        }
    }
    __syncthreads();

    int dq = tid >> 3;
    int sq = (tid & 7) * 4;
#pragma unroll
    for (int pass = 0; pass < 8; ++pass) {
        int d = pass * 32 + dq;
        __half2 a = __halves2half2(__float2half_rn(es[sq + 0][d]), __float2half_rn(es[sq + 1][d]));
        __half2 b = __halves2half2(__float2half_rn(es[sq + 2][d]), __float2half_rn(es[sq + 3][d]));
        uint2 uh; uh.x = *(uint32_t*)&a; uh.y = *(uint32_t*)&b;
        *(uint2*)&g_ETh[((size_t)n * DD + d) * SS + s0 + sq] = uh;
    }
}

// colsum over hi plane (matches GEMM1's operand exactly)
__global__ void colsum_kernel()
{
    int r = blockIdx.x * 8 + (threadIdx.x >> 5);
    int l = threadIdx.x & 31;
    const uint4* ph = (const uint4*)(g_ETh + (size_t)r * SS);
    float s = 0.0f;
#pragma unroll
    for (int c = 0; c < 2; ++c) {
        uint4 a = ph[l + c * 32];
        const __half2* pa = (const __half2*)&a;
#pragma unroll
        for (int j = 0; j < 4; ++j) {
            float2 fa = __half22float2(pa[j]);
            s += fa.x + fa.y;
        }
    }
#pragma unroll
    for (int off = 16; off > 0; off >>= 1) s += __shfl_xor_sync(0xffffffff, s, off);
    if (l == 0) g_cs[r] = s;
}

// ---------------- warp-MMA fp16 batched GEMM (KC=32, round-13 structure) -----
// 3-stage cp.async ring, wait_group 1. Single-pass fp16-hi A.
// BF32: B fp32 (in-kernel convert to hi) else fp16 hi plane via cp.async.
// OMODE: 0 = fp32 out + bias; 1 = half hi + row scale; 2 = half hi.
#define A_STR 80
#define B_STR 272
#define SM_AH 0
#define SM_BH 10240
#define SM_STAGE 27648          // 10240 (A) + 32*272 (B) = 18944 -> pad to 16B: use exact
#undef SM_STAGE
#define SM_STAGE 18944
#define SM_PIPE (3 * SM_STAGE)

template<bool BF32, int OMODE>
__global__ __launch_bounds__(256, 2)
void gemm_mma(const __half* __restrict__ Ahg,
              const void* __restrict__ Bg,
              void* __restrict__ Cg,
              int K, int ldb, int ldc,
              long aStride, int aMod, long bStride, int bMod, long cStride,
              const float* __restrict__ scaleBase, int scaleMod,
              const float* __restrict__ bias)
{
    extern __shared__ __align__(16) char smem[];

    int z = blockIdx.z;
    const __half* Ah = Ahg + (long)(aMod ? (z % aMod) : z) * aStride;
    int m0 = blockIdx.y * 128, n0 = blockIdx.x * 128;

    int tid = threadIdx.x, lane = tid & 31, wid = tid >> 5;
    int wm = wid >> 1, wn = wid & 1;       // warp tile 32(M) x 64(N)

    uint32_t sb = smem_u32(smem);

    // A cp.async map (KC=32 halves per row = 64B): 2 threads/row, 32B each
    int arow = tid >> 1;
    int au = (tid & 1) * 2;
    const __half* aSrcH = Ah + (size_t)(m0 + arow) * K + au * 8;
    uint32_t aDstH = sb + SM_AH + arow * A_STR + au * 16;

    // B maps (32 rows x 128 cols)
    int brow;
    int bnb = 0, bu = 0;
    const __half* bSrcH = nullptr;
    const float* bPtr = nullptr;
    uint32_t bDst = 0, bOffH = 0;
    if (BF32) {
        brow = tid >> 3; bnb = (tid & 7) * 16;
        bPtr = (const float*)Bg + (long)(bMod ? (z % bMod) : z) * bStride
             + (long)brow * ldb + n0 + bnb;
        bOffH = SM_BH + brow * B_STR + bnb * 2;
    } else {
        brow = tid >> 3; bu = (tid & 7) * 2;
        bSrcH = (const __half*)Bg + (long)(bMod ? (z % bMod) : z) * bStride
              + (size_t)brow * ldb + n0 + bu * 8;
        bDst = sb + SM_BH + brow * B_STR + bu * 16;
    }

    uint32_t aFH[2], bFH[4];
#pragma unroll
    for (int t = 0; t < 2; ++t)
        aFH[t] = SM_AH + (uint32_t)((wm * 32 + t * 16 + (lane & 15)) * A_STR + (lane >> 4) * 16);
#pragma unroll
    for (int p = 0; p < 4; ++p)
        bFH[p] = SM_BH + (uint32_t)((lane & 15) * B_STR + (wn * 64 + p * 16 + (lane >> 4) * 8) * 2);

    float acc[2][8][4];
#pragma unroll
    for (int t = 0; t < 2; ++t)
#pragma unroll
        for (int nt = 0; nt < 8; ++nt)
#pragma unroll
            for (int j = 0; j < 4; ++j) acc[t][nt][j] = 0.0f;

    auto cpAsyncLoad = [&](int kc, uint32_t bufOff) {
        const __half* sh = aSrcH + kc * 32;
        CP16(aDstH + bufOff, sh);
        CP16(aDstH + bufOff + 16, sh + 8);
        if (!BF32) {
            const __half* sbp = bSrcH + (size_t)kc * 32 * ldb;
            CP16(bDst + bufOff, sbp);
            CP16(bDst + bufOff + 16, sbp + 8);
        }
    };
    auto bConvStore = [&](int kc, uint32_t bufOff) {
        const float* bp = bPtr + (size_t)kc * 32 * ldb;
        float4 vb0 = *(const float4*)(bp);
        float4 vb1 = *(const float4*)(bp + 4);
        float4 vb2 = *(const float4*)(bp + 8);
        float4 vb3 = *(const float4*)(bp + 12);
        *(uint4*)(smem + bufOff + bOffH) = make_uint4(
            pack2h(vb0.x, vb0.y), pack2h(vb0.z, vb0.w),
            pack2h(vb1.x, vb1.y), pack2h(vb1.z, vb1.w));
        *(uint4*)(smem + bufOff + bOffH + 16) = make_uint4(
            pack2h(vb2.x, vb2.y), pack2h(vb2.z, vb2.w),
            pack2h(vb3.x, vb3.y), pack2h(vb3.z, vb3.w));
    };
    auto mmaStep = [&](int kk, uint32_t bufOff) {
        uint32_t ah[2][4], bf[4][4];
#pragma unroll
        for (int t = 0; t < 2; ++t)
            ldsm4(ah[t], sb + bufOff + aFH[t] + kk * 32);
#pragma unroll
        for (int p = 0; p < 4; ++p)
            ldsm4t(bf[p], sb + bufOff + bFH[p] + kk * 16 * B_STR);
#pragma unroll
        for (int t = 0; t < 2; ++t)
#pragma unroll
            for (int nt = 0; nt < 8; ++nt)
                mma16816(acc[t][nt], ah[t], &bf[nt >> 1][(nt & 1) * 2]);
    };

    int KT = K / 32;

    cpAsyncLoad(0, 0);
    CP_COMMIT();
    cpAsyncLoad(1, SM_STAGE);
    CP_COMMIT();
    if (BF32) bConvStore(0, 0);

    int cur = 0;
    for (int kc = 0; kc < KT; ++kc) {
        uint32_t curOff = (uint32_t)cur * SM_STAGE;
        CP_WAIT1();
        __syncthreads();
        int pf = kc + 2;
        if (pf < KT) {
            int pfs = pf - 3 * (pf / 3);
            cpAsyncLoad(pf, (uint32_t)pfs * SM_STAGE);
            CP_COMMIT();
        }
        mmaStep(0, curOff);
        if (BF32 && kc + 1 < KT) {
            int ns = (cur + 1 == 3) ? 0 : cur + 1;
            bConvStore(kc + 1, (uint32_t)ns * SM_STAGE);
        }
        mmaStep(1, curOff);
        cur = (cur + 1 == 3) ? 0 : cur + 1;
    }

    // ---- epilogue ----
    const float* sp = (OMODE == 1)
        ? scaleBase + (long)(scaleMod ? (z % scaleMod) : z) * DD : nullptr;
#pragma unroll
    for (int t = 0; t < 2; ++t) {
        int row = m0 + wm * 32 + t * 16 + (lane >> 2);
        float s0 = 1.0f, s1 = 1.0f;
        if (OMODE == 1) { s0 = 1.0f / sp[row]; s1 = 1.0f / sp[row + 8]; }
#pragma unroll
        for (int nt = 0; nt < 8; ++nt) {
            int col = n0 + wn * 64 + nt * 8 + (lane & 3) * 2;
            float v0 = acc[t][nt][0] * s0, v1 = acc[t][nt][1] * s0;
            float v2 = acc[t][nt][2] * s1, v3 = acc[t][nt][3] * s1;
            if (OMODE == 0) {
                float* C = (float*)Cg + (long)z * cStride;
                float2 bb = *(const float2*)(bias + col);
                *(float2*)&C[(long)row * ldc + col] = make_float2(v0 + bb.x, v1 + bb.y);
                *(float2*)&C[(long)(row + 8) * ldc + col] = make_float2(v2 + bb.x, v3 + bb.y);
            } else {
                __half* Ch = (__half*)Cg + (long)z * cStride;
                *(__half2*)&Ch[(long)row * ldc + col] =
                    __halves2half2(__float2half_rn(v0), __float2half_rn(v1));
                *(__half2*)&Ch[(long)(row + 8) * ldc + col] =
                    __halves2half2(__float2half_rn(v2), __float2half_rn(v3));
            }
        }
    }
}

// ---------------- launch -----------------------------------------------------
extern "C" void kernel_launch(void* const* d_in, const int* in_sizes, int n_in,
                              void* d_out, int out_size)
{
    const float* value = (const float*)d_in[0];
    const float* emb   = (const float*)d_in[1];
    const float* Wqk   = (const float*)d_in[2];
    const float* bqk   = (const float*)d_in[3];
    const float* Wv    = (const float*)d_in[4];
    const float* bv    = (const float*)d_in[5];
    float* out = (float*)d_out;

    void *pqh, *pETh, *pcs, *pkvh, *pPh;
    cudaGetSymbolAddress(&pqh, g_qh);
    cudaGetSymbolAddress(&pETh, g_ETh);
    cudaGetSymbolAddress(&pcs, g_cs);
    cudaGetSymbolAddress(&pkvh, g_kvh);
    cudaGetSymbolAddress(&pPh, g_Ph);

    static int smemSet = 0;
    if (!smemSet) {
        cudaFuncSetAttribute(gemm_mma<true, 1>,  cudaFuncAttributeMaxDynamicSharedMemorySize, SM_PIPE);
        cudaFuncSetAttribute(gemm_mma<true, 2>,  cudaFuncAttributeMaxDynamicSharedMemorySize, SM_PIPE);
        cudaFuncSetAttribute(gemm_mma<false, 0>, cudaFuncAttributeMaxDynamicSharedMemorySize, SM_PIPE);
        smemSet = 1;
    }

    qk_kernel<<<NN * (SS / QROWS), 256>>>(emb, Wqk, bqk);
    colsum_kernel<<<NN * DD / 8, 256>>>();

    // GEMM1: kv = (ETh @ value_hi) / colsum  -> kv hi plane (single-pass A)
    gemm_mma<true, 1><<<dim3(2, 2, BB * NN), 256, SM_PIPE>>>(
        (const __half*)pETh, value,
        pkvh,
        SS, DD, DD,
        (long)DD * SS, NN,
        (long)SS * DD, 0,
        (long)DD * DD,
        (const float*)pcs, NN, nullptr);

    // GEMM2: P = kv @ Wv_hi  -> P hi plane
    gemm_mma<true, 2><<<dim3(2, 2, BB * NN), 256, SM_PIPE>>>(
        (const __half*)pkvh, Wv,
        pPh,
        DD, DD, DD,
        (long)DD * DD, 0,
        0L, 0,
        (long)DD * DD,
        nullptr, 0, nullptr);

    // GEMM3: out = q @ P + bv  (fp32 out)
    gemm_mma<false, 0><<<dim3(2, 4, BB * NN), 256, SM_PIPE>>>(
        (const __half*)pqh, pPh,
        out,
        DD, DD, DD,
        (long)SS * DD, NN,
        (long)DD * DD, 0,
        (long)SS * DD,
        nullptr, 0, bv);
}

// round 17
// speedup vs baseline: 1.3710x; 1.1360x over previous
#include <cuda_runtime.h>
#include <cuda_fp16.h>
#include <cstdint>
#include <math.h>

#define BB 32
#define NN 12
#define SS 512
#define DD 256
#define AA 96

// ---------------- scratch (device globals, fp16 hi planes) -------------------
static __device__ __align__(16) __half g_qh[NN * SS * DD];
static __device__ __align__(16) __half g_ETh[NN * DD * SS];
static __device__ float g_cs[NN * DD];
static __device__ __align__(16) __half g_kvh[(size_t)BB * NN * DD * DD];
static __device__ __align__(16) __half g_Ph[(size_t)BB * NN * DD * DD];
static __device__ __align__(16) __half g_Wvh[DD * DD];

// ---------------- helpers ----------------------------------------------------
__device__ __forceinline__ uint32_t smem_u32(const void* p) {
    uint32_t a;
    asm("{ .reg .u64 t; cvta.to.shared.u64 t, %1; cvt.u32.u64 %0, t; }" : "=r"(a) : "l"(p));
    return a;
}
__device__ __forceinline__ void ldsm4(uint32_t* r, uint32_t a) {
    asm volatile("ldmatrix.sync.aligned.m8n8.x4.shared.b16 {%0,%1,%2,%3}, [%4];"
                 : "=r"(r[0]), "=r"(r[1]), "=r"(r[2]), "=r"(r[3]) : "r"(a));
}
__device__ __forceinline__ void ldsm4t(uint32_t* r, uint32_t a) {
    asm volatile("ldmatrix.sync.aligned.m8n8.x4.trans.shared.b16 {%0,%1,%2,%3}, [%4];"
                 : "=r"(r[0]), "=r"(r[1]), "=r"(r[2]), "=r"(r[3]) : "r"(a));
}
__device__ __forceinline__ void mma16816(float* c, const uint32_t* a, const uint32_t* b) {
    asm volatile("mma.sync.aligned.m16n8k16.row.col.f32.f16.f16.f32 "
                 "{%0,%1,%2,%3}, {%4,%5,%6,%7}, {%8,%9}, {%0,%1,%2,%3};"
                 : "+f"(c[0]), "+f"(c[1]), "+f"(c[2]), "+f"(c[3])
                 : "r"(a[0]), "r"(a[1]), "r"(a[2]), "r"(a[3]), "r"(b[0]), "r"(b[1]));
}
__device__ __forceinline__ uint32_t pack2h(float x, float y) {
    __half2 hv; hv.x = __float2half_rn(x); hv.y = __float2half_rn(y);
    return *(uint32_t*)&hv;
}
#define CP16(dst, src) \
    asm volatile("cp.async.cg.shared.global [%0], [%1], 16;" :: "r"(dst), "l"(src))
#define CP_COMMIT() asm volatile("cp.async.commit_group;" ::: "memory")
#define CP_WAIT2()  asm volatile("cp.async.wait_group 2;" ::: "memory")

// ---------------- qk kernel: q hi plane + ET hi plane -------------------------
#define QROWS 32
__global__ __launch_bounds__(256)
void qk_kernel(const float* __restrict__ emb,
               const float* __restrict__ Wqk,
               const float* __restrict__ bqk)
{
    int n = blockIdx.x / (SS / QROWS);
    int s0 = (blockIdx.x % (SS / QROWS)) * QROWS;

    __shared__ float se[QROWS][AA];
    __shared__ float es[QROWS][257];

    int tid = threadIdx.x;
    for (int i = tid; i < QROWS * AA; i += 256)
        se[i / AA][i % AA] = emb[((size_t)(n * SS + s0)) * AA + i];
    __syncthreads();

    int sy = tid >> 5;
    int dx = tid & 31;

    float acc[4][8];
#pragma unroll
    for (int j = 0; j < 8; ++j) {
        float b = bqk[j * 32 + dx];
#pragma unroll
        for (int i = 0; i < 4; ++i) acc[i][j] = b;
    }
#pragma unroll 2
    for (int a = 0; a < AA; ++a) {
        float w[8];
#pragma unroll
        for (int j = 0; j < 8; ++j) w[j] = Wqk[a * DD + j * 32 + dx];
        float sv0 = se[sy * 4 + 0][a], sv1 = se[sy * 4 + 1][a];
        float sv2 = se[sy * 4 + 2][a], sv3 = se[sy * 4 + 3][a];
#pragma unroll
        for (int j = 0; j < 8; ++j) {
            acc[0][j] = fmaf(sv0, w[j], acc[0][j]);
            acc[1][j] = fmaf(sv1, w[j], acc[1][j]);
            acc[2][j] = fmaf(sv2, w[j], acc[2][j]);
            acc[3][j] = fmaf(sv3, w[j], acc[3][j]);
        }
    }

#pragma unroll
    for (int i = 0; i < 4; ++i) {
        float loc = 0.0f;
#pragma unroll
        for (int j = 0; j < 8; ++j) { acc[i][j] = expf(acc[i][j]); loc += acc[i][j]; }
#pragma unroll
        for (int off = 16; off > 0; off >>= 1) loc += __shfl_xor_sync(0xffffffff, loc, off);
        float inv = 1.0f / loc;
        int s = s0 + sy * 4 + i;
#pragma unroll
        for (int j = 0; j < 8; ++j) {
            size_t idx = ((size_t)(n * SS + s)) * DD + j * 32 + dx;
            g_qh[idx] = __float2half_rn(acc[i][j] * inv);
            es[sy * 4 + i][j * 32 + dx] = acc[i][j];
        }
    }
    __syncthreads();

    int dq = tid >> 3;
    int sq = (tid & 7) * 4;
#pragma unroll
    for (int pass = 0; pass < 8; ++pass) {
        int d = pass * 32 + dq;
        __half2 a = __halves2half2(__float2half_rn(es[sq + 0][d]), __float2half_rn(es[sq + 1][d]));
        __half2 b = __halves2half2(__float2half_rn(es[sq + 2][d]), __float2half_rn(es[sq + 3][d]));
        uint2 uh; uh.x = *(uint32_t*)&a; uh.y = *(uint32_t*)&b;
        *(uint2*)&g_ETh[((size_t)n * DD + d) * SS + s0 + sq] = uh;
    }
}

// colsum over hi plane
__global__ void colsum_kernel()
{
    int r = blockIdx.x * 8 + (threadIdx.x >> 5);
    int l = threadIdx.x & 31;
    const uint4* ph = (const uint4*)(g_ETh + (size_t)r * SS);
    float s = 0.0f;
#pragma unroll
    for (int c = 0; c < 2; ++c) {
        uint4 a = ph[l + c * 32];
        const __half2* pa = (const __half2*)&a;
#pragma unroll
        for (int j = 0; j < 4; ++j) {
            float2 fa = __half22float2(pa[j]);
            s += fa.x + fa.y;
        }
    }
#pragma unroll
    for (int off = 16; off > 0; off >>= 1) s += __shfl_xor_sync(0xffffffff, s, off);
    if (l == 0) g_cs[r] = s;
}

// Wv fp32 -> fp16 plane (one-time, 64K elems)
__global__ void convW_kernel(const float* __restrict__ Wv)
{
    int i = (blockIdx.x * 256 + threadIdx.x) * 4;
    float4 v = *(const float4*)(Wv + i);
    uint2 u; u.x = pack2h(v.x, v.y); u.y = pack2h(v.z, v.w);
    *(uint2*)&g_Wvh[i] = u;
}

// ---------------- warp-MMA fp16 batched GEMM (KC=32, 4-stage ring) -----------
// BF32: B fp32 with pipelined LDG->conv->STS (regs loaded one chunk ahead);
// else fp16 B plane via cp.async.
// OMODE: 0 = fp32 out + bias; 1 = half hi + row scale; 2 = half hi.
#define A_STR 80
#define B_STR 272
#define SM_AH 0
#define SM_BH 10240
#define SM_STAGE 18944
#define NSTAGE 4
#define SM_PIPE (NSTAGE * SM_STAGE)

template<bool BF32, int OMODE>
__global__ __launch_bounds__(256, 2)
void gemm_mma(const __half* __restrict__ Ahg,
              const void* __restrict__ Bg,
              void* __restrict__ Cg,
              int K, int ldb, int ldc,
              long aStride, int aMod, long bStride, int bMod, long cStride,
              const float* __restrict__ scaleBase, int scaleMod,
              const float* __restrict__ bias)
{
    extern __shared__ __align__(16) char smem[];

    int z = blockIdx.z;
    const __half* Ah = Ahg + (long)(aMod ? (z % aMod) : z) * aStride;
    int m0 = blockIdx.y * 128, n0 = blockIdx.x * 128;

    int tid = threadIdx.x, lane = tid & 31, wid = tid >> 5;
    int wm = wid >> 1, wn = wid & 1;       // warp tile 32(M) x 64(N)

    uint32_t sb = smem_u32(smem);

    // A cp.async map
    int arow = tid >> 1;
    int au = (tid & 1) * 2;
    const __half* aSrcH = Ah + (size_t)(m0 + arow) * K + au * 8;
    uint32_t aDstH = sb + SM_AH + arow * A_STR + au * 16;

    // B maps (32 rows x 128 cols)
    int brow = tid >> 3;
    const __half* bSrcH = nullptr;
    const float* bPtr = nullptr;
    uint32_t bDst = 0, bOffH = 0;
    if (BF32) {
        int bnb = (tid & 7) * 16;
        bPtr = (const float*)Bg + (long)(bMod ? (z % bMod) : z) * bStride
             + (long)brow * ldb + n0 + bnb;
        bOffH = SM_BH + brow * B_STR + bnb * 2;
    } else {
        int bu = (tid & 7) * 2;
        bSrcH = (const __half*)Bg + (long)(bMod ? (z % bMod) : z) * bStride
              + (size_t)brow * ldb + n0 + bu * 8;
        bDst = sb + SM_BH + brow * B_STR + bu * 16;
    }

    uint32_t aFH[2], bFH[4];
#pragma unroll
    for (int t = 0; t < 2; ++t)
        aFH[t] = SM_AH + (uint32_t)((wm * 32 + t * 16 + (lane & 15)) * A_STR + (lane >> 4) * 16);
#pragma unroll
    for (int p = 0; p < 4; ++p)
        bFH[p] = SM_BH + (uint32_t)((lane & 15) * B_STR + (wn * 64 + p * 16 + (lane >> 4) * 8) * 2);

    float acc[2][8][4];
#pragma unroll
    for (int t = 0; t < 2; ++t)
#pragma unroll
        for (int nt = 0; nt < 8; ++nt)
#pragma unroll
            for (int j = 0; j < 4; ++j) acc[t][nt][j] = 0.0f;

    float4 vbReg[4];   // BF32 conv staging (loaded one chunk ahead)

    auto cpAsyncLoad = [&](int kc, uint32_t bufOff) {
        const __half* sh = aSrcH + kc * 32;
        CP16(aDstH + bufOff, sh);
        CP16(aDstH + bufOff + 16, sh + 8);
        if (!BF32) {
            const __half* sbp = bSrcH + (size_t)kc * 32 * ldb;
            CP16(bDst + bufOff, sbp);
            CP16(bDst + bufOff + 16, sbp + 8);
        }
    };
    auto bLoadRegs = [&](int kc) {
        const float* bp = bPtr + (size_t)kc * 32 * ldb;
        vbReg[0] = *(const float4*)(bp);
        vbReg[1] = *(const float4*)(bp + 4);
        vbReg[2] = *(const float4*)(bp + 8);
        vbReg[3] = *(const float4*)(bp + 12);
    };
    auto bStore = [&](uint32_t bufOff) {
        *(uint4*)(smem + bufOff + bOffH) = make_uint4(
            pack2h(vbReg[0].x, vbReg[0].y), pack2h(vbReg[0].z, vbReg[0].w),
            pack2h(vbReg[1].x, vbReg[1].y), pack2h(vbReg[1].z, vbReg[1].w));
        *(uint4*)(smem + bufOff + bOffH + 16) = make_uint4(
            pack2h(vbReg[2].x, vbReg[2].y), pack2h(vbReg[2].z, vbReg[2].w),
            pack2h(vbReg[3].x, vbReg[3].y), pack2h(vbReg[3].z, vbReg[3].w));
    };
    auto mmaStep = [&](int kk, uint32_t bufOff) {
        uint32_t ah[2][4], bf[4][4];
#pragma unroll
        for (int t = 0; t < 2; ++t)
            ldsm4(ah[t], sb + bufOff + aFH[t] + kk * 32);
#pragma unroll
        for (int p = 0; p < 4; ++p)
            ldsm4t(bf[p], sb + bufOff + bFH[p] + kk * 16 * B_STR);
#pragma unroll
        for (int t = 0; t < 2; ++t)
#pragma unroll
            for (int nt = 0; nt < 8; ++nt)
                mma16816(acc[t][nt], ah[t], &bf[nt >> 1][(nt & 1) * 2]);
    };

    int KT = K / 32;

    // prologue: 3 A(/B) loads in flight; BF32: conv chunk0 stored, chunk1 regs loaded
    cpAsyncLoad(0, 0);
    CP_COMMIT();
    cpAsyncLoad(1, SM_STAGE);
    CP_COMMIT();
    cpAsyncLoad(2, 2 * SM_STAGE);
    CP_COMMIT();
    if (BF32) {
        bLoadRegs(0);
        bStore(0);
        bLoadRegs(1);
    }

    for (int kc = 0; kc < KT; ++kc) {
        uint32_t curOff = (uint32_t)(kc & 3) * SM_STAGE;
        CP_WAIT2();              // group kc complete (2 newer pending)
        __syncthreads();
        int pf = kc + 3;
        if (pf < KT) {
            cpAsyncLoad(pf, (uint32_t)(pf & 3) * SM_STAGE);
            CP_COMMIT();
        } else {
            CP_COMMIT();         // keep group accounting aligned
        }
        mmaStep(0, curOff);
        if (BF32) {
            if (kc + 1 < KT) bStore((uint32_t)((kc + 1) & 3) * SM_STAGE);
            if (kc + 2 < KT) bLoadRegs(kc + 2);
        }
        mmaStep(1, curOff);
    }

    // ---- epilogue ----
    const float* sp = (OMODE == 1)
        ? scaleBase + (long)(scaleMod ? (z % scaleMod) : z) * DD : nullptr;
#pragma unroll
    for (int t = 0; t < 2; ++t) {
        int row = m0 + wm * 32 + t * 16 + (lane >> 2);
        float s0 = 1.0f, s1 = 1.0f;
        if (OMODE == 1) { s0 = 1.0f / sp[row]; s1 = 1.0f / sp[row + 8]; }
#pragma unroll
        for (int nt = 0; nt < 8; ++nt) {
            int col = n0 + wn * 64 + nt * 8 + (lane & 3) * 2;
            float v0 = acc[t][nt][0] * s0, v1 = acc[t][nt][1] * s0;
            float v2 = acc[t][nt][2] * s1, v3 = acc[t][nt][3] * s1;
            if (OMODE == 0) {
                float* C = (float*)Cg + (long)z * cStride;
                float2 bb = *(const float2*)(bias + col);
                *(float2*)&C[(long)row * ldc + col] = make_float2(v0 + bb.x, v1 + bb.y);
                *(float2*)&C[(long)(row + 8) * ldc + col] = make_float2(v2 + bb.x, v3 + bb.y);
            } else {
                __half* Ch = (__half*)Cg + (long)z * cStride;
                *(__half2*)&Ch[(long)row * ldc + col] =
                    __halves2half2(__float2half_rn(v0), __float2half_rn(v1));
                *(__half2*)&Ch[(long)(row + 8) * ldc + col] =
                    __halves2half2(__float2half_rn(v2), __float2half_rn(v3));
            }
        }
    }
}

// ---------------- launch -----------------------------------------------------
extern "C" void kernel_launch(void* const* d_in, const int* in_sizes, int n_in,
                              void* d_out, int out_size)
{
    const float* value = (const float*)d_in[0];
    const float* emb   = (const float*)d_in[1];
    const float* Wqk   = (const float*)d_in[2];
    const float* bqk   = (const float*)d_in[3];
    const float* Wv    = (const float*)d_in[4];
    const float* bv    = (const float*)d_in[5];
    float* out = (float*)d_out;

    void *pqh, *pETh, *pcs, *pkvh, *pPh, *pWvh;
    cudaGetSymbolAddress(&pqh, g_qh);
    cudaGetSymbolAddress(&pETh, g_ETh);
    cudaGetSymbolAddress(&pcs, g_cs);
    cudaGetSymbolAddress(&pkvh, g_kvh);
    cudaGetSymbolAddress(&pPh, g_Ph);
    cudaGetSymbolAddress(&pWvh, g_Wvh);

    static int smemSet = 0;
    if (!smemSet) {
        cudaFuncSetAttribute(gemm_mma<true, 1>,  cudaFuncAttributeMaxDynamicSharedMemorySize, SM_PIPE);
        cudaFuncSetAttribute(gemm_mma<false, 2>, cudaFuncAttributeMaxDynamicSharedMemorySize, SM_PIPE);
        cudaFuncSetAttribute(gemm_mma<false, 0>, cudaFuncAttributeMaxDynamicSharedMemorySize, SM_PIPE);
        smemSet = 1;
    }

    qk_kernel<<<NN * (SS / QROWS), 256>>>(emb, Wqk, bqk);
    colsum_kernel<<<NN * DD / 8, 256>>>();
    convW_kernel<<<DD * DD / 1024, 256>>>(Wv);

    // GEMM1: kv = (ETh @ value_hi) / colsum  -> kv hi plane
    gemm_mma<true, 1><<<dim3(2, 2, BB * NN), 256, SM_PIPE>>>(
        (const __half*)pETh, value,
        pkvh,
        SS, DD, DD,
        (long)DD * SS, NN,
        (long)SS * DD, 0,
        (long)DD * DD,
        (const float*)pcs, NN, nullptr);

    // GEMM2: P = kv @ Wvh  -> P hi plane (pure cp.async)
    gemm_mma<false, 2><<<dim3(2, 2, BB * NN), 256, SM_PIPE>>>(
        (const __half*)pkvh, pWvh,
        pPh,
        DD, DD, DD,
        (long)DD * DD, 0,
        0L, 0,
        (long)DD * DD,
        nullptr, 0, nullptr);

    // GEMM3: out = q @ P + bv  (fp32 out)
    gemm_mma<false, 0><<<dim3(2, 4, BB * NN), 256, SM_PIPE>>>(
        (const __half*)pqh, pPh,
        out,
        DD, DD, DD,
        (long)SS * DD, NN,
        (long)DD * DD, 0,
        (long)SS * DD,
        nullptr, 0, bv);
}